// round 1
// baseline (speedup 1.0000x reference)
#include <cuda_runtime.h>
#include <math.h>

#define Bb 4
#define Nn 4096
#define NP1 (Nn + 1)
#define INF 256
#define OUTF 128
#define NEG 0.01f
#define NCH 32
#define CHUNK (Nn / NCH)

// ---------------- scratch (static device globals; no runtime alloc) ----------
__device__ float g_feats[(size_t)Bb * Nn * OUTF];           // 8 MB
__device__ float g_f1[Bb * Nn], g_f2[Bb * Nn];
__device__ float g_a[Bb * Nn], g_c[Bb * Nn];                // exp(f1), exp(.01 f1)
__device__ float g_bv[Bb * Nn], g_dv[Bb * Nn];              // exp(f2), exp(.01 f2)
__device__ float g_sf1[Bb * Nn], g_sf2[Bb * Nn];
__device__ int   g_p1[Bb * Nn], g_p2[Bb * Nn];
__device__ float g_PA[Bb * NP1], g_PC[Bb * NP1];
__device__ float g_gj[Bb * Nn], g_hj[Bb * Nn];
__device__ int   g_pos[Bb * Nn];
__device__ float g_chG[(size_t)Bb * NCH * OUTF], g_chH[(size_t)Bb * NCH * OUTF];
__device__ float g_PG[(size_t)Bb * NP1 * OUTF];             // 8.4 MB
__device__ float g_PH[(size_t)Bb * NP1 * OUTF];             // 8.4 MB

// ---------------- K1: feats = X @ W_fc  (fp32 SGEMM, 128x128x16 tiles) -------
__global__ void __launch_bounds__(256) k_sgemm(const float* __restrict__ A,
                                               const float* __restrict__ W) {
    __shared__ float sA[16][128];
    __shared__ float sB[16][128];
    const int bm  = blockIdx.x * 128;
    const int tid = threadIdx.x;
    const int tx  = tid & 15, ty = tid >> 4;
    float acc[8][8];
#pragma unroll
    for (int i = 0; i < 8; i++)
#pragma unroll
        for (int j = 0; j < 8; j++) acc[i][j] = 0.f;

    for (int k0 = 0; k0 < INF; k0 += 16) {
#pragma unroll
        for (int l = 0; l < 2; l++) {
            int q = tid + l * 256;
            int row = q >> 2, kq = (q & 3) << 2;
            float4 v = *(const float4*)&A[(size_t)(bm + row) * INF + k0 + kq];
            sA[kq + 0][row] = v.x; sA[kq + 1][row] = v.y;
            sA[kq + 2][row] = v.z; sA[kq + 3][row] = v.w;
        }
#pragma unroll
        for (int l = 0; l < 2; l++) {
            int q = tid + l * 256;
            int kk = q >> 5, c4 = (q & 31) << 2;
            *(float4*)&sB[kk][c4] = *(const float4*)&W[(size_t)(k0 + kk) * OUTF + c4];
        }
        __syncthreads();
#pragma unroll
        for (int kk = 0; kk < 16; kk++) {
            float4 a0 = *(const float4*)&sA[kk][ty * 8];
            float4 a1 = *(const float4*)&sA[kk][ty * 8 + 4];
            float4 b0 = *(const float4*)&sB[kk][tx * 8];
            float4 b1 = *(const float4*)&sB[kk][tx * 8 + 4];
            float ra[8] = {a0.x, a0.y, a0.z, a0.w, a1.x, a1.y, a1.z, a1.w};
            float rb[8] = {b0.x, b0.y, b0.z, b0.w, b1.x, b1.y, b1.z, b1.w};
#pragma unroll
            for (int i = 0; i < 8; i++)
#pragma unroll
                for (int j = 0; j < 8; j++) acc[i][j] += ra[i] * rb[j];
        }
        __syncthreads();
    }
#pragma unroll
    for (int i = 0; i < 8; i++) {
        int row = bm + ty * 8 + i;
#pragma unroll
        for (int j = 0; j < 8; j += 4) {
            *(float4*)&g_feats[(size_t)row * OUTF + tx * 8 + j] =
                make_float4(acc[i][j], acc[i][j + 1], acc[i][j + 2], acc[i][j + 3]);
        }
    }
}

// ---------------- K2: f1, f2 and the 4 exp families per row ------------------
__global__ void k_rowdots(const float* __restrict__ wl, const float* __restrict__ bl,
                          const float* __restrict__ wr, const float* __restrict__ br) {
    int gw   = (blockIdx.x * blockDim.x + threadIdx.x) >> 5;
    int lane = threadIdx.x & 31;
    if (gw >= Bb * Nn) return;
    const float* fr = g_feats + (size_t)gw * OUTF;
    float s1 = 0.f, s2 = 0.f;
#pragma unroll
    for (int l = 0; l < 4; l++) {
        float v = fr[lane + 32 * l];
        s1 += v * wl[lane + 32 * l];
        s2 += v * wr[lane + 32 * l];
    }
#pragma unroll
    for (int o = 16; o > 0; o >>= 1) {
        s1 += __shfl_down_sync(0xffffffffu, s1, o);
        s2 += __shfl_down_sync(0xffffffffu, s2, o);
    }
    if (lane == 0) {
        float f1 = s1 + bl[0], f2 = s2 + br[0];
        g_f1[gw] = f1; g_f2[gw] = f2;
        g_a[gw]  = expf(f1);       g_c[gw]  = expf(NEG * f1);
        g_bv[gw] = expf(f2);       g_dv[gw] = expf(NEG * f2);
    }
}

// ---------------- K3: per-batch bitonic sort of f1 and f2 (key + perm) -------
__global__ void __launch_bounds__(1024) k_sort() {
    __shared__ float sk[Nn];
    __shared__ int   sv[Nn];
    int b = blockIdx.x >> 1;
    int which = blockIdx.x & 1;
    const float* src = which ? g_f2 : g_f1;
    int tid = threadIdx.x;
    for (int i = tid; i < Nn; i += 1024) { sk[i] = src[b * Nn + i]; sv[i] = i; }
    __syncthreads();
    for (int k = 2; k <= Nn; k <<= 1) {
        for (int j = k >> 1; j > 0; j >>= 1) {
            for (int i = tid; i < Nn; i += 1024) {
                int ixj = i ^ j;
                if (ixj > i) {
                    bool up = ((i & k) == 0);
                    float ki = sk[i], kj = sk[ixj];
                    if ((ki > kj) == up) {
                        sk[i] = kj; sk[ixj] = ki;
                        int t = sv[i]; sv[i] = sv[ixj]; sv[ixj] = t;
                    }
                }
            }
            __syncthreads();
        }
    }
    float* dk = which ? g_sf2 : g_sf1;
    int*   dv = which ? g_p2  : g_p1;
    for (int i = tid; i < Nn; i += 1024) { dk[b * Nn + i] = sk[i]; dv[b * Nn + i] = sv[i]; }
}

// ---------------- K4: exclusive prefix sums of a, c in f1-sorted order -------
__global__ void __launch_bounds__(1024) k_scan_ac() {
    const int b = blockIdx.x;
    const int tid = threadIdx.x;
    const int lane = tid & 31, wid = tid >> 5;
    __shared__ float wsA[32], wsC[32];
    const int base = b * Nn, baseP = b * NP1;
    const int k0 = tid * 4;
    float va[4], vc[4];
#pragma unroll
    for (int l = 0; l < 4; l++) {
        int idx = g_p1[base + k0 + l];
        va[l] = g_a[base + idx];
        vc[l] = g_c[base + idx];
    }
    float ia[4], ic[4];
    ia[0] = va[0]; ic[0] = vc[0];
#pragma unroll
    for (int l = 1; l < 4; l++) { ia[l] = ia[l - 1] + va[l]; ic[l] = ic[l - 1] + vc[l]; }
    float sa = ia[3], sc = ic[3];
    float pa = sa, pc = sc;
#pragma unroll
    for (int o = 1; o < 32; o <<= 1) {
        float ua = __shfl_up_sync(0xffffffffu, pa, o);
        float uc = __shfl_up_sync(0xffffffffu, pc, o);
        if (lane >= o) { pa += ua; pc += uc; }
    }
    if (lane == 31) { wsA[wid] = pa; wsC[wid] = pc; }
    __syncthreads();
    if (wid == 0) {
        float xa = wsA[lane], xc = wsC[lane];
#pragma unroll
        for (int o = 1; o < 32; o <<= 1) {
            float ua = __shfl_up_sync(0xffffffffu, xa, o);
            float uc = __shfl_up_sync(0xffffffffu, xc, o);
            if (lane >= o) { xa += ua; xc += uc; }
        }
        wsA[lane] = xa; wsC[lane] = xc;
    }
    __syncthreads();
    float offA = (wid ? wsA[wid - 1] : 0.f) + (pa - sa);
    float offC = (wid ? wsC[wid - 1] : 0.f) + (pc - sc);
    if (tid == 0) { g_PA[baseP] = 0.f; g_PC[baseP] = 0.f; }
#pragma unroll
    for (int l = 0; l < 4; l++) {
        g_PA[baseP + k0 + l + 1] = offA + ia[l];
        g_PC[baseP + k0 + l + 1] = offC + ic[l];
    }
}

// ---------------- K5: per-column denominator D_j -> g_j, h_j -----------------
__global__ void k_dgh() {
    int i = blockIdx.x * blockDim.x + threadIdx.x;
    if (i >= Bb * Nn) return;
    int b = i >> 12;
    float t = -g_f2[i];
    const float* s = g_sf1 + b * Nn;
    int lo = 0, hi = Nn;
    while (lo < hi) { int mid = (lo + hi) >> 1; if (s[mid] < t) lo = mid + 1; else hi = mid; }
    int bp = b * NP1;
    float suffA = g_PA[bp + Nn] - g_PA[bp + lo];  // a>0: monotone, no cancellation
    float sumC  = g_PC[bp + lo];
    float bvv = g_bv[i], dvv = g_dv[i];
    float inv = 1.0f / (bvv * suffA + dvv * sumC);
    g_gj[i] = bvv * inv;
    g_hj[i] = dvv * inv;
}

// ---------------- K5b: per-row split position in f2-sorted order -------------
__global__ void k_pos() {
    int i = blockIdx.x * blockDim.x + threadIdx.x;
    if (i >= Bb * Nn) return;
    int b = i >> 12;
    float t = -g_f1[i];
    const float* s = g_sf2 + b * Nn;
    int lo = 0, hi = Nn;
    while (lo < hi) { int mid = (lo + hi) >> 1; if (s[mid] < t) lo = mid + 1; else hi = mid; }
    g_pos[i] = lo;
}

// ---------------- K6a: chunk partial sums of G = g*feats, H = h*feats --------
__global__ void __launch_bounds__(128) k_chunksum() {
    int b = blockIdx.x / NCH, ch = blockIdx.x % NCH;
    int f = threadIdx.x;
    int base = b * Nn;
    float sg = 0.f, sh = 0.f;
    int k0 = ch * CHUNK;
#pragma unroll 4
    for (int k = k0; k < k0 + CHUNK; k++) {
        int j = g_p2[base + k];
        float gv = g_gj[base + j], hv = g_hj[base + j];
        float v  = g_feats[((size_t)(base + j)) * OUTF + f];
        sg += gv * v; sh += hv * v;
    }
    g_chG[(size_t)blockIdx.x * OUTF + f] = sg;
    g_chH[(size_t)blockIdx.x * OUTF + f] = sh;
}

// ---------------- K6b: scan chunk sums -> chunk offsets + totals row ---------
__global__ void k_chunkscan() {
    int tid = threadIdx.x;           // 512 = Bb * OUTF
    int b = tid >> 7, f = tid & 127;
    float rg = 0.f, rh = 0.f;
    for (int ch = 0; ch < NCH; ch++) {
        size_t idx = (size_t)(b * NCH + ch) * OUTF + f;
        float tg = g_chG[idx], th = g_chH[idx];
        g_chG[idx] = rg; g_chH[idx] = rh;
        rg += tg; rh += th;
    }
    size_t idN = ((size_t)b * NP1 + Nn) * OUTF + f;   // row N = totals
    g_PG[idN] = rg; g_PH[idN] = rh;
}

// ---------------- K6c: write full exclusive vector prefixes PG, PH -----------
__global__ void __launch_bounds__(128) k_writeprefix() {
    int b = blockIdx.x / NCH, ch = blockIdx.x % NCH;
    int f = threadIdx.x;
    int base = b * Nn;
    float rg = g_chG[(size_t)blockIdx.x * OUTF + f];
    float rh = g_chH[(size_t)blockIdx.x * OUTF + f];
    int k0 = ch * CHUNK;
    for (int k = k0; k < k0 + CHUNK; k++) {
        size_t o = ((size_t)b * NP1 + k) * OUTF + f;
        g_PG[o] = rg; g_PH[o] = rh;
        int j = g_p2[base + k];
        float v = g_feats[((size_t)(base + j)) * OUTF + f];
        rg += g_gj[base + j] * v;
        rh += g_hj[base + j] * v;
    }
}

// ---------------- K7: out[i,:] = a_i * (TG - PG[pos]) + c_i * PH[pos] --------
__global__ void __launch_bounds__(256) k_out(float* __restrict__ out) {
    int r = blockIdx.x * 2 + (threadIdx.x >> 7);
    int f = threadIdx.x & 127;
    int b = r >> 12;
    int pos = g_pos[r];
    size_t pb = (size_t)b * NP1;
    float TG = g_PG[(pb + Nn) * OUTF + f];
    float pg = g_PG[(pb + pos) * OUTF + f];
    float ph = g_PH[(pb + pos) * OUTF + f];
    out[(size_t)r * OUTF + f] = g_a[r] * (TG - pg) + g_c[r] * ph;
}

// ---------------- launch ------------------------------------------------------
extern "C" void kernel_launch(void* const* d_in, const int* in_sizes, int n_in,
                              void* d_out, int out_size) {
    const float* X  = (const float*)d_in[0];  // [4,4096,256]
    const float* W  = (const float*)d_in[1];  // [256,128]
    const float* wl = (const float*)d_in[2];
    const float* bl = (const float*)d_in[3];
    const float* wr = (const float*)d_in[4];
    const float* br = (const float*)d_in[5];
    float* out = (float*)d_out;

    k_sgemm<<<(Bb * Nn) / 128, 256>>>(X, W);
    k_rowdots<<<(Bb * Nn * 32) / 256, 256>>>(wl, bl, wr, br);
    k_sort<<<Bb * 2, 1024>>>();
    k_scan_ac<<<Bb, 1024>>>();
    k_dgh<<<(Bb * Nn) / 256, 256>>>();
    k_pos<<<(Bb * Nn) / 256, 256>>>();
    k_chunksum<<<Bb * NCH, 128>>>();
    k_chunkscan<<<1, 512>>>();
    k_writeprefix<<<Bb * NCH, 128>>>();
    k_out<<<(Bb * Nn) / 2, 256>>>(out);
}